// round 1
// baseline (speedup 1.0000x reference)
#include <cuda_runtime.h>
#include <cuda_bf16.h>
#include <cstdint>

#define NB 32
#define NC 384
#define NT 1024
#define MAXLEN 8192
#define COUT (NC + 2)
#define MAX_DUR 10000

// Scratch (no allocations allowed): per-position expansion map + per-batch totals.
// map element: .x = (tok << 1) | valid, .y = idx_in | (len << 16)
__device__ int2 g_map[NB * MAXLEN];
__device__ int  g_total[NB];
__device__ int  g_is64;

// ---------------------------------------------------------------------------
// Kernel 0: detect whether `duration` is stored as int64 or int32.
// Values are in [0,8), so if int64, every odd 32-bit word of the first 1024
// entries is 0. If int32, those words are random durations (P(all zero)~8^-512).
// ---------------------------------------------------------------------------
__global__ void detect_kernel(const int* __restrict__ dur) {
    int odd_nonzero = 0;
    for (int i = threadIdx.x; i < 1024; i += 32) {
        if (dur[2 * i + 1] != 0) odd_nonzero = 1;
    }
    odd_nonzero = __any_sync(0xffffffffu, odd_nonzero);
    if (threadIdx.x == 0) g_is64 = odd_nonzero ? 0 : 1;
}

// ---------------------------------------------------------------------------
// Kernel 1: per-batch inclusive scan of clipped durations + scatter expansion
// map. One block per batch, 1024 threads (one per token).
// ---------------------------------------------------------------------------
__global__ void scan_expand_kernel(const int* __restrict__ dur32) {
    const int b = blockIdx.x;
    const int t = threadIdx.x;           // token index, 0..1023
    const int lane = t & 31;
    const int warp = t >> 5;

    int d;
    if (g_is64) {
        // int64 little-endian: low word at int index 2*(b*NT+t)
        d = dur32[2 * (b * NT + t)];
    } else {
        d = dur32[b * NT + t];
    }
    if (d < 0) d = -d;
    if (d < 1) d = 1;
    if (d > MAX_DUR) d = MAX_DUR;

    // inclusive scan over 1024 threads
    int v = d;
    #pragma unroll
    for (int o = 1; o < 32; o <<= 1) {
        int n = __shfl_up_sync(0xffffffffu, v, o);
        if (lane >= o) v += n;
    }
    __shared__ int wsum[32];
    if (lane == 31) wsum[warp] = v;
    __syncthreads();
    if (warp == 0) {
        int w = wsum[lane];
        #pragma unroll
        for (int o = 1; o < 32; o <<= 1) {
            int n = __shfl_up_sync(0xffffffffu, w, o);
            if (lane >= o) w += n;
        }
        wsum[lane] = w;
    }
    __syncthreads();

    const int end_  = v + (warp > 0 ? wsum[warp - 1] : 0);
    const int start = end_ - d;

    __shared__ int s_total;
    if (t == NT - 1) {
        s_total = end_;
        g_total[b] = end_;
    }
    __syncthreads();
    const int total = s_total;

    int2* map = g_map + b * MAXLEN;

    // scatter: token t owns positions [start, end) — disjoint across threads
    for (int j = 0; j < d; j++) {
        const int pos = start + j;
        if (pos >= MAXLEN) break;
        map[pos] = make_int2((t << 1) | 1, j | (d << 16));
    }
    // tail fill: positions >= total are invalid (output must be zero)
    const int tstart = total < MAXLEN ? total : MAXLEN;
    for (int pos = tstart + t; pos < MAXLEN; pos += NT) {
        map[pos] = make_int2(0, 0);
    }
}

// ---------------------------------------------------------------------------
// Kernel 2: gather + write output. Each thread handles 4 consecutive output
// positions (float4 stores). Grid: (p-tiles=8, batch=32, c-chunks=4).
// ---------------------------------------------------------------------------
#define CCHUNK 97   // ceil(386/4)

__global__ void __launch_bounds__(256) gather_kernel(const float* __restrict__ x,
                                                     float* __restrict__ out) {
    const int b  = blockIdx.y;
    const int p0 = (blockIdx.x * 256 + threadIdx.x) * 4;

    const int4* mp = reinterpret_cast<const int4*>(g_map + b * MAXLEN + p0);
    const int4 m0 = mp[0];
    const int4 m1 = mp[1];

    const int tok0 = m0.x >> 1, tok1 = m0.z >> 1;
    const int tok2 = m1.x >> 1, tok3 = m1.z >> 1;
    const float f0 = (m0.x & 1) ? 1.f : 0.f;
    const float f1 = (m0.z & 1) ? 1.f : 0.f;
    const float f2 = (m1.x & 1) ? 1.f : 0.f;
    const float f3 = (m1.z & 1) ? 1.f : 0.f;

    const float* xb = x + (size_t)b * NC * NT;
    float* ob = out + (size_t)b * COUT * MAXLEN + p0;

    const int cbeg = blockIdx.z * CCHUNK;
    const int cend = min(cbeg + CCHUNK, COUT);
    const int clim = min(cend, NC);

    for (int c = cbeg; c < clim; c++) {
        const float* row = xb + (size_t)c * NT;
        float4 r;
        r.x = row[tok0] * f0;
        r.y = row[tok1] * f1;
        r.z = row[tok2] * f2;
        r.w = row[tok3] * f3;
        *reinterpret_cast<float4*>(ob + (size_t)c * MAXLEN) = r;
    }
    if (NC >= cbeg && NC < cend) {
        float4 r;
        r.x = (float)(m0.y & 0xffff) * f0;
        r.y = (float)(m0.w & 0xffff) * f1;
        r.z = (float)(m1.y & 0xffff) * f2;
        r.w = (float)(m1.w & 0xffff) * f3;
        *reinterpret_cast<float4*>(ob + (size_t)NC * MAXLEN) = r;
    }
    if (NC + 1 >= cbeg && NC + 1 < cend) {
        float4 r;
        r.x = (float)((unsigned)m0.y >> 16) * f0;
        r.y = (float)((unsigned)m0.w >> 16) * f1;
        r.z = (float)((unsigned)m1.y >> 16) * f2;
        r.w = (float)((unsigned)m1.w >> 16) * f3;
        *reinterpret_cast<float4*>(ob + (size_t)(NC + 1) * MAXLEN) = r;
    }
}

// ---------------------------------------------------------------------------
// Kernel 3: mel_len output (cast to output dtype = float)
// ---------------------------------------------------------------------------
__global__ void mel_kernel(float* __restrict__ dst) {
    const int b = threadIdx.x;
    if (b < NB) dst[b] = (float)g_total[b];
}

extern "C" void kernel_launch(void* const* d_in, const int* in_sizes, int n_in,
                              void* d_out, int out_size) {
    const float* x   = (const float*)d_in[0];
    const int*   dur = (const int*)d_in[1];
    float*       out = (float*)d_out;

    detect_kernel<<<1, 32>>>(dur);
    scan_expand_kernel<<<NB, NT>>>(dur);
    gather_kernel<<<dim3(MAXLEN / (256 * 4), NB, 4), 256>>>(x, out);

    const long long main_elems = (long long)NB * COUT * MAXLEN;
    if ((long long)out_size >= main_elems + NB) {
        mel_kernel<<<1, 32>>>(out + main_elems);
    }
    (void)in_sizes; (void)n_in;
}